// round 4
// baseline (speedup 1.0000x reference)
#include <cuda_runtime.h>
#include <cuda_bf16.h>
#include <math.h>

// Problem constants
#define BATCH   2
#define SEQ     2048
#define HID     1024
#define HEADS   16
#define DH      64
#define MTOT    (BATCH * SEQ)          // 4096

// Scratch (device globals — no allocation allowed)
__device__ float g_qkv[3u * BATCH * HEADS * SEQ * DH];   // [c,b,h,s,d]  ~50MB
__device__ float g_attn[(size_t)BATCH * SEQ * HID];      // [b,s,h*64+d] ~17MB

// ---------------------------------------------------------------------------
// Tiled fp32 GEMM: C[M,N] = A[M,K] @ B[K,N] + bias[N]
// 128x128 tile, BK=8, 256 threads, 8x8 per-thread micro-tile.
// mode 0: plain write to C
// mode 1: scatter epilogue into g_qkv ([3,B,H,S,Dh] layout), C unused
// mode 2: A is ignored; read from g_attn; plain write to C
// ---------------------------------------------------------------------------
__global__ __launch_bounds__(256) void gemm_bias(
    const float* __restrict__ A, const float* __restrict__ Bm,
    const float* __restrict__ bias, float* __restrict__ C,
    int M, int N, int K, int mode)
{
    __shared__ float As[8][128];
    __shared__ float Bs[8][128];

    const int tid = threadIdx.x;
    const int tx = tid & 15;          // 0..15  (col group)
    const int ty = tid >> 4;          // 0..15  (row group)
    const int bm = blockIdx.y * 128;
    const int bn = blockIdx.x * 128;

    const float* Ause = (mode == 2) ? g_attn : A;

    // loader mapping
    const int arow = tid >> 1;             // 0..127
    const int acol = (tid & 1) * 4;        // 0 or 4
    const int brow = tid >> 5;             // 0..7
    const int bcol = (tid & 31) * 4;       // 0..124

    const float* Aptr = Ause + (size_t)(bm + arow) * K + acol;
    const float* Bptr = Bm + (size_t)brow * N + bn + bcol;

    float acc[8][8];
#pragma unroll
    for (int i = 0; i < 8; i++)
#pragma unroll
        for (int j = 0; j < 8; j++) acc[i][j] = 0.f;

    for (int kt = 0; kt < K; kt += 8) {
        float4 a4 = *(const float4*)(Aptr + kt);
        float4 b4 = *(const float4*)(Bptr + (size_t)kt * N);

        As[acol + 0][arow] = a4.x;
        As[acol + 1][arow] = a4.y;
        As[acol + 2][arow] = a4.z;
        As[acol + 3][arow] = a4.w;
        *(float4*)&Bs[brow][bcol] = b4;
        __syncthreads();

#pragma unroll
        for (int kk = 0; kk < 8; ++kk) {
            float4 a0 = *(const float4*)&As[kk][ty * 4];
            float4 a1 = *(const float4*)&As[kk][ty * 4 + 64];
            float4 b0 = *(const float4*)&Bs[kk][tx * 4];
            float4 b1 = *(const float4*)&Bs[kk][tx * 4 + 64];
            float af[8] = {a0.x, a0.y, a0.z, a0.w, a1.x, a1.y, a1.z, a1.w};
            float bf[8] = {b0.x, b0.y, b0.z, b0.w, b1.x, b1.y, b1.z, b1.w};
#pragma unroll
            for (int i = 0; i < 8; i++)
#pragma unroll
                for (int j = 0; j < 8; j++)
                    acc[i][j] = fmaf(af[i], bf[j], acc[i][j]);
        }
        __syncthreads();
    }

    // epilogue
#pragma unroll
    for (int i = 0; i < 8; i++) {
        const int m = bm + ty * 4 + (i & 3) + ((i >> 2) << 6);
#pragma unroll
        for (int j = 0; j < 8; j++) {
            const int n = bn + tx * 4 + (j & 3) + ((j >> 2) << 6);
            float v = acc[i][j] + bias[n];
            if (mode == 1) {
                // n -> (c,h,d), m -> (b,s); write g_qkv[((c*B+b)*H+h)*S + s][d]
                const int c = n >> 10;
                const int h = (n >> 6) & 15;
                const int d = n & 63;
                const int bb = m >> 11;
                const int ss = m & 2047;
                g_qkv[((size_t)((c * BATCH + bb) * HEADS + h) * SEQ + ss) * DH + d] = v;
            } else {
                C[(size_t)m * N + n] = v;
            }
        }
    }
}

// ---------------------------------------------------------------------------
// Flash attention: per-(b,h), 64-query tile per CTA, stream 64-key tiles.
// 256 threads, 4x4 per-thread micro-tile for both QK^T and PV.
// Writes g_attn in [b, s, h*64+d] layout (ready for output projection).
// ---------------------------------------------------------------------------
#define QS_F   (64 * 64)   // Qs: stride 64 (reads are 2-way broadcast per warp)
#define KS_F   (64 * 65)   // Ks: stride 65 (lane-varying row reads need padding)
#define VS_F   (64 * 64)   // Vs: stride 64 (column reads conflict-free)
#define PS_F   (64 * 64)   // Ps: stride 64 (row reads broadcast)
#define ATTN_SMEM ((QS_F + KS_F + VS_F + PS_F) * 4)   // 65792 bytes

__global__ __launch_bounds__(256) void attn_kernel()
{
    extern __shared__ float sm[];
    float* Qs = sm;
    float* Ks = sm + QS_F;
    float* Vs = sm + QS_F + KS_F;
    float* Ps = sm + QS_F + KS_F + VS_F;

    const int tid = threadIdx.x;
    const int tx = tid & 15;
    const int ty = tid >> 4;
    const int bh = blockIdx.y;
    const int b = bh >> 4;
    const int h = bh & 15;
    const int q0 = blockIdx.x << 6;

    const float* Qp = g_qkv + (size_t)((0 * BATCH + b) * HEADS + h) * (SEQ * DH);
    const float* Kp = g_qkv + (size_t)((1 * BATCH + b) * HEADS + h) * (SEQ * DH);
    const float* Vp = g_qkv + (size_t)((2 * BATCH + b) * HEADS + h) * (SEQ * DH);

    // Load Q tile, pre-scaled by 1/sqrt(64) = 0.125
    for (int i = tid; i < 1024; i += 256) {
        const int r = i >> 4;
        const int c4 = (i & 15) << 2;
        float4 v = *(const float4*)(Qp + (size_t)(q0 + r) * DH + c4);
        float* q = Qs + r * 64 + c4;
        q[0] = v.x * 0.125f; q[1] = v.y * 0.125f;
        q[2] = v.z * 0.125f; q[3] = v.w * 0.125f;
    }

    float o[4][4];
    float m_i[4], l_i[4];
#pragma unroll
    for (int i = 0; i < 4; i++) {
        m_i[i] = -3.0e38f; l_i[i] = 0.f;
#pragma unroll
        for (int j = 0; j < 4; j++) o[i][j] = 0.f;
    }

    for (int kt = 0; kt < SEQ / 64; ++kt) {
        __syncthreads();  // previous iter's readers done (also covers Q load)

        // load K,V tiles
        const float* kp = Kp + (size_t)(kt << 6) * DH;
        const float* vp = Vp + (size_t)(kt << 6) * DH;
        for (int i = tid; i < 1024; i += 256) {
            const int r = i >> 4;
            const int c4 = (i & 15) << 2;
            float4 kv = *(const float4*)(kp + r * DH + c4);
            float* kd = Ks + r * 65 + c4;
            kd[0] = kv.x; kd[1] = kv.y; kd[2] = kv.z; kd[3] = kv.w;
            float4 vv = *(const float4*)(vp + r * DH + c4);
            float* vd = Vs + r * 64 + c4;
            vd[0] = vv.x; vd[1] = vv.y; vd[2] = vv.z; vd[3] = vv.w;
        }
        __syncthreads();

        // S = (Q * scale) @ K^T   (4x4 per thread over k=64)
        float s[4][4];
#pragma unroll
        for (int i = 0; i < 4; i++)
#pragma unroll
            for (int j = 0; j < 4; j++) s[i][j] = 0.f;

        const float* qb = Qs + (ty * 4) * 64;
        const float* kb = Ks + (tx * 4) * 65;
#pragma unroll 8
        for (int k = 0; k < 64; ++k) {
            float a0 = qb[0 * 64 + k], a1 = qb[1 * 64 + k];
            float a2 = qb[2 * 64 + k], a3 = qb[3 * 64 + k];
            float c0 = kb[0 * 65 + k], c1 = kb[1 * 65 + k];
            float c2 = kb[2 * 65 + k], c3 = kb[3 * 65 + k];
            s[0][0] = fmaf(a0, c0, s[0][0]); s[0][1] = fmaf(a0, c1, s[0][1]);
            s[0][2] = fmaf(a0, c2, s[0][2]); s[0][3] = fmaf(a0, c3, s[0][3]);
            s[1][0] = fmaf(a1, c0, s[1][0]); s[1][1] = fmaf(a1, c1, s[1][1]);
            s[1][2] = fmaf(a1, c2, s[1][2]); s[1][3] = fmaf(a1, c3, s[1][3]);
            s[2][0] = fmaf(a2, c0, s[2][0]); s[2][1] = fmaf(a2, c1, s[2][1]);
            s[2][2] = fmaf(a2, c2, s[2][2]); s[2][3] = fmaf(a2, c3, s[2][3]);
            s[3][0] = fmaf(a3, c0, s[3][0]); s[3][1] = fmaf(a3, c1, s[3][1]);
            s[3][2] = fmaf(a3, c2, s[3][2]); s[3][3] = fmaf(a3, c3, s[3][3]);
        }

        // online softmax update (rows of the 16-lane tx-group)
#pragma unroll
        for (int i = 0; i < 4; i++) {
            float rmax = fmaxf(fmaxf(s[i][0], s[i][1]), fmaxf(s[i][2], s[i][3]));
#pragma unroll
            for (int off = 1; off < 16; off <<= 1)
                rmax = fmaxf(rmax, __shfl_xor_sync(0xffffffffu, rmax, off));
            const float mnew = fmaxf(m_i[i], rmax);
            const float alpha = __expf(m_i[i] - mnew);
            float rsum = 0.f;
#pragma unroll
            for (int j = 0; j < 4; j++) {
                float p = __expf(s[i][j] - mnew);
                s[i][j] = p;
                rsum += p;
            }
#pragma unroll
            for (int off = 1; off < 16; off <<= 1)
                rsum += __shfl_xor_sync(0xffffffffu, rsum, off);
            l_i[i] = l_i[i] * alpha + rsum;
            m_i[i] = mnew;
#pragma unroll
            for (int j = 0; j < 4; j++) o[i][j] *= alpha;
        }

        // stage P tile
#pragma unroll
        for (int i = 0; i < 4; i++)
#pragma unroll
            for (int j = 0; j < 4; j++)
                Ps[(ty * 4 + i) * 64 + tx * 4 + j] = s[i][j];
        __syncthreads();

        // O += P @ V
        const float* pb = Ps + (ty * 4) * 64;
        const float* vb = Vs + tx * 4;
#pragma unroll 8
        for (int t = 0; t < 64; ++t) {
            float p0 = pb[0 * 64 + t], p1 = pb[1 * 64 + t];
            float p2 = pb[2 * 64 + t], p3 = pb[3 * 64 + t];
            float v0 = vb[t * 64 + 0], v1 = vb[t * 64 + 1];
            float v2 = vb[t * 64 + 2], v3 = vb[t * 64 + 3];
            o[0][0] = fmaf(p0, v0, o[0][0]); o[0][1] = fmaf(p0, v1, o[0][1]);
            o[0][2] = fmaf(p0, v2, o[0][2]); o[0][3] = fmaf(p0, v3, o[0][3]);
            o[1][0] = fmaf(p1, v0, o[1][0]); o[1][1] = fmaf(p1, v1, o[1][1]);
            o[1][2] = fmaf(p1, v2, o[1][2]); o[1][3] = fmaf(p1, v3, o[1][3]);
            o[2][0] = fmaf(p2, v0, o[2][0]); o[2][1] = fmaf(p2, v1, o[2][1]);
            o[2][2] = fmaf(p2, v2, o[2][2]); o[2][3] = fmaf(p2, v3, o[2][3]);
            o[3][0] = fmaf(p3, v0, o[3][0]); o[3][1] = fmaf(p3, v1, o[3][1]);
            o[3][2] = fmaf(p3, v2, o[3][2]); o[3][3] = fmaf(p3, v3, o[3][3]);
        }
    }

    // finalize + write [b, s, h*64+d]
#pragma unroll
    for (int i = 0; i < 4; i++) {
        const float inv = 1.0f / l_i[i];
        const int row = q0 + ty * 4 + i;
        float* dst = g_attn + ((size_t)b * SEQ + row) * HID + h * DH + tx * 4;
        dst[0] = o[i][0] * inv;
        dst[1] = o[i][1] * inv;
        dst[2] = o[i][2] * inv;
        dst[3] = o[i][3] * inv;
    }
}

// ---------------------------------------------------------------------------
extern "C" void kernel_launch(void* const* d_in, const int* in_sizes, int n_in,
                              void* d_out, int out_size)
{
    const float* x     = (const float*)d_in[0];
    const float* Wqkv  = (const float*)d_in[1];
    const float* bqkv  = (const float*)d_in[2];
    const float* Wout  = (const float*)d_in[3];
    const float* bout  = (const float*)d_in[4];
    float* out = (float*)d_out;

    // Needed for >48KB dynamic smem; idempotent, immediate (capture-safe).
    cudaFuncSetAttribute(attn_kernel,
                         cudaFuncAttributeMaxDynamicSharedMemorySize, ATTN_SMEM);

    // 1) QKV projection + bias, scattered into [3,B,H,S,Dh]
    gemm_bias<<<dim3(3 * HID / 128, MTOT / 128), 256>>>(
        x, Wqkv, bqkv, nullptr, MTOT, 3 * HID, HID, 1);

    // 2) Attention -> g_attn [B,S,H*Dh]
    attn_kernel<<<dim3(SEQ / 64, BATCH * HEADS), 256, ATTN_SMEM>>>();

    // 3) Output projection + bias
    gemm_bias<<<dim3(HID / 128, MTOT / 128), 256>>>(
        nullptr, Wout, bout, out, MTOT, HID, HID, 2);
}

// round 9
// speedup vs baseline: 1.3797x; 1.3797x over previous
#include <cuda_runtime.h>
#include <cuda_bf16.h>
#include <cstdint>
#include <math.h>

// Problem constants
#define BATCH   2
#define SEQ     2048
#define HID     1024
#define HEADS   16
#define DH      64
#define MTOT    (BATCH * SEQ)          // 4096

// ---------------------------------------------------------------------------
// Scratch (device globals — no allocation allowed)
// ---------------------------------------------------------------------------
__device__ float g_qkv[(size_t)3 * BATCH * HEADS * SEQ * DH];        // fp32 [c,b,h,s,d]
__device__ __nv_bfloat16 g_attn_h[(size_t)MTOT * HID];
__device__ __nv_bfloat16 g_attn_l[(size_t)MTOT * HID];
__device__ __nv_bfloat16 g_x_h[(size_t)MTOT * HID];
__device__ __nv_bfloat16 g_x_l[(size_t)MTOT * HID];
__device__ __nv_bfloat16 g_wq_h[(size_t)3 * HID * HID];   // [3072][1024] = W_qkv^T
__device__ __nv_bfloat16 g_wq_l[(size_t)3 * HID * HID];
__device__ __nv_bfloat16 g_wo_h[(size_t)HID * HID];       // [1024][1024] = W_out^T
__device__ __nv_bfloat16 g_wo_l[(size_t)HID * HID];

// ---------------------------------------------------------------------------
// PTX helpers (baseline sm_103 ISA only: ldmatrix + mma.sync, NO tcgen05)
// ---------------------------------------------------------------------------
__device__ __forceinline__ uint32_t smem_u32(const void* p) {
    uint32_t a;
    asm("{ .reg .u64 t; cvta.to.shared.u64 t, %1; cvt.u32.u64 %0, t; }" : "=r"(a) : "l"(p));
    return a;
}
#define SWZ(o) ((o) ^ (((o) >> 3) & 0x70))
#define STS128(addr, v) \
    asm volatile("st.shared.v4.b32 [%0], {%1,%2,%3,%4};" \
                 :: "r"(addr), "r"(v.x), "r"(v.y), "r"(v.z), "r"(v.w) : "memory")

#define LDSM_X4(r, addr) \
    asm volatile("ldmatrix.sync.aligned.m8n8.x4.shared.b16 {%0,%1,%2,%3}, [%4];" \
        : "=r"((r)[0]), "=r"((r)[1]), "=r"((r)[2]), "=r"((r)[3]) : "r"(addr))
#define LDSM_X2(r, addr) \
    asm volatile("ldmatrix.sync.aligned.m8n8.x2.shared.b16 {%0,%1}, [%2];" \
        : "=r"((r)[0]), "=r"((r)[1]) : "r"(addr))
#define MMA16816(d, a, b) \
    asm volatile("mma.sync.aligned.m16n8k16.row.col.f32.bf16.bf16.f32 " \
        "{%0,%1,%2,%3}, {%4,%5,%6,%7}, {%8,%9}, {%0,%1,%2,%3};" \
        : "+f"((d)[0]), "+f"((d)[1]), "+f"((d)[2]), "+f"((d)[3]) \
        : "r"((a)[0]), "r"((a)[1]), "r"((a)[2]), "r"((a)[3]), \
          "r"((b)[0]), "r"((b)[1]))

// ---------------------------------------------------------------------------
// Prep kernels: fp32 -> bf16 hi/lo split (and weight transpose)
// ---------------------------------------------------------------------------
__global__ __launch_bounds__(256) void split_f32(
    const float* __restrict__ s, __nv_bfloat16* __restrict__ hi,
    __nv_bfloat16* __restrict__ lo, int n4)
{
    int i = blockIdx.x * 256 + threadIdx.x;
    if (i >= n4) return;
    float4 v = ((const float4*)s)[i];
    union { __nv_bfloat16 b[4]; uint2 u; } ph, pl;
    float f[4] = {v.x, v.y, v.z, v.w};
#pragma unroll
    for (int j = 0; j < 4; j++) {
        __nv_bfloat16 h = __float2bfloat16(f[j]);
        ph.b[j] = h;
        pl.b[j] = __float2bfloat16(f[j] - __bfloat162float(h));
    }
    ((uint2*)hi)[i] = ph.u;
    ((uint2*)lo)[i] = pl.u;
}

// W[K][N] -> Th/Tl[N][K]  (transpose + split)
__global__ void transpose_split(const float* __restrict__ W,
                                __nv_bfloat16* __restrict__ Th,
                                __nv_bfloat16* __restrict__ Tl, int K, int N)
{
    __shared__ float t[32][33];
    const int k0 = blockIdx.y * 32, n0 = blockIdx.x * 32;
    const int tx = threadIdx.x, ty = threadIdx.y;
    for (int j = ty; j < 32; j += 8)
        t[j][tx] = W[(size_t)(k0 + j) * N + n0 + tx];
    __syncthreads();
    for (int j = ty; j < 32; j += 8) {
        float v = t[tx][j];
        __nv_bfloat16 h = __float2bfloat16(v);
        Th[(size_t)(n0 + j) * K + k0 + tx] = h;
        Tl[(size_t)(n0 + j) * K + k0 + tx] = __float2bfloat16(v - __bfloat162float(h));
    }
}

// ---------------------------------------------------------------------------
// mma.sync GEMM with bf16 hi/lo split (3 passes), fp32 accumulate.
// C[M,N] = A[M,K] @ B[N,K]^T + bias[N]
// 128x128 CTA tile, K-chunk 64, 256 threads = 8 warps (2M x 4N, 64x32 each).
// mode 0: plain write to C.  mode 1: scatter into g_qkv ([3,B,H,S,Dh]).
// ---------------------------------------------------------------------------
#define GT_SMEM (4 * 16384 + 1024)

__global__ __launch_bounds__(256, 2) void gemm_tc(
    const __nv_bfloat16* __restrict__ Ah, const __nv_bfloat16* __restrict__ Al,
    const __nv_bfloat16* __restrict__ Bh, const __nv_bfloat16* __restrict__ Bl,
    const float* __restrict__ bias, float* __restrict__ C,
    int M, int N, int K, int mode)
{
    extern __shared__ char smraw[];
    const uint32_t smem0 = smem_u32(smraw);
    const uint32_t tile  = (smem0 + 1023u) & ~1023u;   // 1024-aligned tiles
    const uint32_t sA_h = tile, sA_l = tile + 16384;
    const uint32_t sB_h = tile + 32768, sB_l = tile + 49152;

    const int tid  = threadIdx.x;
    const int wid  = tid >> 5, lane = tid & 31;
    const int wm   = wid & 1, wn = wid >> 1;        // 2 x 4 warp grid
    const int bm   = blockIdx.y << 7, bn = blockIdx.x << 7;

    // per-thread fragment base offsets (bytes within a 128x64-bf16 SW128 tile)
    uint32_t a_base[4], b_base[4];
#pragma unroll
    for (int mi = 0; mi < 4; mi++) {
        const int rowA = wm * 64 + mi * 16 + (lane & 15);
        a_base[mi] = (uint32_t)rowA * 128 + (((uint32_t)lane >> 4) << 4);
    }
    const int l15 = lane & 15;
#pragma unroll
    for (int ni = 0; ni < 4; ni++) {
        const int rowB = wn * 32 + ni * 8 + (l15 & 7);
        b_base[ni] = (uint32_t)rowB * 128 + (((uint32_t)l15 >> 3) << 4);
    }

    float d[4][4][4];
#pragma unroll
    for (int mi = 0; mi < 4; mi++)
#pragma unroll
        for (int ni = 0; ni < 4; ni++)
#pragma unroll
            for (int k = 0; k < 4; k++) d[mi][ni][k] = 0.f;

    for (int kc = 0; kc < K; kc += 64) {
        __syncthreads();   // previous chunk's readers done
        // ---- stage 4 tiles (128 rows x 64 bf16 = 128B/row, SW128) ----
#pragma unroll
        for (int i = 0; i < 4; i++) {
            const int idx = tid + (i << 8);        // 0..1023
            const int r = idx >> 3, c = idx & 7;   // row, 16B-chunk
            const uint32_t so = SWZ((uint32_t)r * 128 + (uint32_t)c * 16);
            const size_t gA = (size_t)(bm + r) * K + kc + c * 8;
            const size_t gB = (size_t)(bn + r) * K + kc + c * 8;
            uint4 v;
            v = *(const uint4*)(Ah + gA); STS128(sA_h + so, v);
            v = *(const uint4*)(Al + gA); STS128(sA_l + so, v);
            v = *(const uint4*)(Bh + gB); STS128(sB_h + so, v);
            v = *(const uint4*)(Bl + gB); STS128(sB_l + so, v);
        }
        __syncthreads();

        // ---- compute: 4 k-steps of 16, 3 split passes each ----
#pragma unroll
        for (int ks = 0; ks < 4; ks++) {
            const uint32_t kb = (uint32_t)ks << 5;   // k-step byte offset
            uint32_t fAh[4][4], fAl[4][4], fBh[4][2], fBl[4][2];
#pragma unroll
            for (int mi = 0; mi < 4; mi++) {
                LDSM_X4(fAh[mi], sA_h + SWZ(a_base[mi] + kb));
                LDSM_X4(fAl[mi], sA_l + SWZ(a_base[mi] + kb));
            }
#pragma unroll
            for (int ni = 0; ni < 4; ni++) {
                LDSM_X2(fBh[ni], sB_h + SWZ(b_base[ni] + kb));
                LDSM_X2(fBl[ni], sB_l + SWZ(b_base[ni] + kb));
            }
#pragma unroll
            for (int mi = 0; mi < 4; mi++)
#pragma unroll
                for (int ni = 0; ni < 4; ni++) {
                    MMA16816(d[mi][ni], fAh[mi], fBh[ni]);
                    MMA16816(d[mi][ni], fAh[mi], fBl[ni]);
                    MMA16816(d[mi][ni], fAl[mi], fBh[ni]);
                }
        }
    }

    // ---- epilogue: direct float2 stores with bias ----
    const int q = lane >> 2;           // 0..7 (row within 8)
    const int cpair = (lane & 3) << 1; // 0,2,4,6
#pragma unroll
    for (int ni = 0; ni < 4; ni++) {
        const int n = bn + wn * 32 + ni * 8 + cpair;
        const float2 bs = *(const float2*)(bias + n);
#pragma unroll
        for (int mi = 0; mi < 4; mi++) {
#pragma unroll
            for (int hh = 0; hh < 2; hh++) {
                const int m = bm + wm * 64 + mi * 16 + q + hh * 8;
                float2 v;
                v.x = d[mi][ni][hh * 2 + 0] + bs.x;
                v.y = d[mi][ni][hh * 2 + 1] + bs.y;
                if (mode == 1) {
                    const int cc = n >> 10, hd = (n >> 6) & 15, dd = n & 63;
                    const int bb = m >> 11, ss = m & 2047;
                    *(float2*)(g_qkv +
                        (((size_t)((cc * 2 + bb) * 16 + hd) * 2048 + ss) * 64 + dd)) = v;
                } else {
                    *(float2*)(C + (size_t)m * N + n) = v;
                }
            }
        }
    }
}

// ---------------------------------------------------------------------------
// Flash attention (fp32 SIMT, unchanged proven math) — epilogue emits
// bf16 hi/lo directly for the output projection.
// ---------------------------------------------------------------------------
#define QS_F   (64 * 64)
#define KS_F   (64 * 65)
#define VS_F   (64 * 64)
#define PS_F   (64 * 64)
#define ATTN_SMEM ((QS_F + KS_F + VS_F + PS_F) * 4)   // 65792 bytes

__global__ __launch_bounds__(256) void attn_kernel()
{
    extern __shared__ float sm[];
    float* Qs = sm;
    float* Ks = sm + QS_F;
    float* Vs = sm + QS_F + KS_F;
    float* Ps = sm + QS_F + KS_F + VS_F;

    const int tid = threadIdx.x;
    const int tx = tid & 15;
    const int ty = tid >> 4;
    const int bh = blockIdx.y;
    const int b = bh >> 4;
    const int h = bh & 15;
    const int q0 = blockIdx.x << 6;

    const float* Qp = g_qkv + (size_t)((0 * BATCH + b) * HEADS + h) * (SEQ * DH);
    const float* Kp = g_qkv + (size_t)((1 * BATCH + b) * HEADS + h) * (SEQ * DH);
    const float* Vp = g_qkv + (size_t)((2 * BATCH + b) * HEADS + h) * (SEQ * DH);

    for (int i = tid; i < 1024; i += 256) {
        const int r = i >> 4;
        const int c4 = (i & 15) << 2;
        float4 v = *(const float4*)(Qp + (size_t)(q0 + r) * DH + c4);
        float* q = Qs + r * 64 + c4;
        q[0] = v.x * 0.125f; q[1] = v.y * 0.125f;
        q[2] = v.z * 0.125f; q[3] = v.w * 0.125f;
    }

    float o[4][4];
    float m_i[4], l_i[4];
#pragma unroll
    for (int i = 0; i < 4; i++) {
        m_i[i] = -3.0e38f; l_i[i] = 0.f;
#pragma unroll
        for (int j = 0; j < 4; j++) o[i][j] = 0.f;
    }

    for (int kt = 0; kt < SEQ / 64; ++kt) {
        __syncthreads();

        const float* kp = Kp + (size_t)(kt << 6) * DH;
        const float* vp = Vp + (size_t)(kt << 6) * DH;
        for (int i = tid; i < 1024; i += 256) {
            const int r = i >> 4;
            const int c4 = (i & 15) << 2;
            float4 kv = *(const float4*)(kp + r * DH + c4);
            float* kd = Ks + r * 65 + c4;
            kd[0] = kv.x; kd[1] = kv.y; kd[2] = kv.z; kd[3] = kv.w;
            float4 vv = *(const float4*)(vp + r * DH + c4);
            float* vd = Vs + r * 64 + c4;
            vd[0] = vv.x; vd[1] = vv.y; vd[2] = vv.z; vd[3] = vv.w;
        }
        __syncthreads();

        float s[4][4];
#pragma unroll
        for (int i = 0; i < 4; i++)
#pragma unroll
            for (int j = 0; j < 4; j++) s[i][j] = 0.f;

        const float* qb = Qs + (ty * 4) * 64;
        const float* kb = Ks + (tx * 4) * 65;
#pragma unroll 8
        for (int k = 0; k < 64; ++k) {
            float a0 = qb[0 * 64 + k], a1 = qb[1 * 64 + k];
            float a2 = qb[2 * 64 + k], a3 = qb[3 * 64 + k];
            float c0 = kb[0 * 65 + k], c1 = kb[1 * 65 + k];
            float c2 = kb[2 * 65 + k], c3 = kb[3 * 65 + k];
            s[0][0] = fmaf(a0, c0, s[0][0]); s[0][1] = fmaf(a0, c1, s[0][1]);
            s[0][2] = fmaf(a0, c2, s[0][2]); s[0][3] = fmaf(a0, c3, s[0][3]);
            s[1][0] = fmaf(a1, c0, s[1][0]); s[1][1] = fmaf(a1, c1, s[1][1]);
            s[1][2] = fmaf(a1, c2, s[1][2]); s[1][3] = fmaf(a1, c3, s[1][3]);
            s[2][0] = fmaf(a2, c0, s[2][0]); s[2][1] = fmaf(a2, c1, s[2][1]);
            s[2][2] = fmaf(a2, c2, s[2][2]); s[2][3] = fmaf(a2, c3, s[2][3]);
            s[3][0] = fmaf(a3, c0, s[3][0]); s[3][1] = fmaf(a3, c1, s[3][1]);
            s[3][2] = fmaf(a3, c2, s[3][2]); s[3][3] = fmaf(a3, c3, s[3][3]);
        }

#pragma unroll
        for (int i = 0; i < 4; i++) {
            float rmax = fmaxf(fmaxf(s[i][0], s[i][1]), fmaxf(s[i][2], s[i][3]));
#pragma unroll
            for (int off = 1; off < 16; off <<= 1)
                rmax = fmaxf(rmax, __shfl_xor_sync(0xffffffffu, rmax, off));
            const float mnew = fmaxf(m_i[i], rmax);
            const float alpha = __expf(m_i[i] - mnew);
            float rsum = 0.f;
#pragma unroll
            for (int j = 0; j < 4; j++) {
                float p = __expf(s[i][j] - mnew);
                s[i][j] = p;
                rsum += p;
            }
#pragma unroll
            for (int off = 1; off < 16; off <<= 1)
                rsum += __shfl_xor_sync(0xffffffffu, rsum, off);
            l_i[i] = l_i[i] * alpha + rsum;
            m_i[i] = mnew;
#pragma unroll
            for (int j = 0; j < 4; j++) o[i][j] *= alpha;
        }

#pragma unroll
        for (int i = 0; i < 4; i++)
#pragma unroll
            for (int j = 0; j < 4; j++)
                Ps[(ty * 4 + i) * 64 + tx * 4 + j] = s[i][j];
        __syncthreads();

        const float* pb = Ps + (ty * 4) * 64;
        const float* vb = Vs + tx * 4;
#pragma unroll 8
        for (int t = 0; t < 64; ++t) {
            float p0 = pb[0 * 64 + t], p1 = pb[1 * 64 + t];
            float p2 = pb[2 * 64 + t], p3 = pb[3 * 64 + t];
            float v0 = vb[t * 64 + 0], v1 = vb[t * 64 + 1];
            float v2 = vb[t * 64 + 2], v3 = vb[t * 64 + 3];
            o[0][0] = fmaf(p0, v0, o[0][0]); o[0][1] = fmaf(p0, v1, o[0][1]);
            o[0][2] = fmaf(p0, v2, o[0][2]); o[0][3] = fmaf(p0, v3, o[0][3]);
            o[1][0] = fmaf(p1, v0, o[1][0]); o[1][1] = fmaf(p1, v1, o[1][1]);
            o[1][2] = fmaf(p1, v2, o[1][2]); o[1][3] = fmaf(p1, v3, o[1][3]);
            o[2][0] = fmaf(p2, v0, o[2][0]); o[2][1] = fmaf(p2, v1, o[2][1]);
            o[2][2] = fmaf(p2, v2, o[2][2]); o[2][3] = fmaf(p2, v3, o[2][3]);
            o[3][0] = fmaf(p3, v0, o[3][0]); o[3][1] = fmaf(p3, v1, o[3][1]);
            o[3][2] = fmaf(p3, v2, o[3][2]); o[3][3] = fmaf(p3, v3, o[3][3]);
        }
    }

    // finalize + bf16 hi/lo write [b, s, h*64+d]
#pragma unroll
    for (int i = 0; i < 4; i++) {
        const float inv = 1.0f / l_i[i];
        const int row = q0 + ty * 4 + i;
        const size_t base = ((size_t)b * SEQ + row) * HID + h * DH + tx * 4;
#pragma unroll
        for (int j = 0; j < 4; j++) {
            const float v = o[i][j] * inv;
            const __nv_bfloat16 hb = __float2bfloat16(v);
            g_attn_h[base + j] = hb;
            g_attn_l[base + j] = __float2bfloat16(v - __bfloat162float(hb));
        }
    }
}

// ---------------------------------------------------------------------------
extern "C" void kernel_launch(void* const* d_in, const int* in_sizes, int n_in,
                              void* d_out, int out_size)
{
    const float* x    = (const float*)d_in[0];
    const float* Wqkv = (const float*)d_in[1];
    const float* bqkv = (const float*)d_in[2];
    const float* Wout = (const float*)d_in[3];
    const float* bout = (const float*)d_in[4];
    float* out = (float*)d_out;

    cudaFuncSetAttribute(attn_kernel,
                         cudaFuncAttributeMaxDynamicSharedMemorySize, ATTN_SMEM);
    cudaFuncSetAttribute(gemm_tc,
                         cudaFuncAttributeMaxDynamicSharedMemorySize, GT_SMEM);

    __nv_bfloat16 *xh, *xl, *wqh, *wql, *woh, *wol, *ath, *atl;
    cudaGetSymbolAddress((void**)&xh,  g_x_h);
    cudaGetSymbolAddress((void**)&xl,  g_x_l);
    cudaGetSymbolAddress((void**)&wqh, g_wq_h);
    cudaGetSymbolAddress((void**)&wql, g_wq_l);
    cudaGetSymbolAddress((void**)&woh, g_wo_h);
    cudaGetSymbolAddress((void**)&wol, g_wo_l);
    cudaGetSymbolAddress((void**)&ath, g_attn_h);
    cudaGetSymbolAddress((void**)&atl, g_attn_l);

    // 0) prep: split x; transpose+split weights
    split_f32<<<(MTOT * HID / 4 + 255) / 256, 256>>>(x, xh, xl, MTOT * HID / 4);
    transpose_split<<<dim3(3 * HID / 32, HID / 32), dim3(32, 8)>>>(Wqkv, wqh, wql, HID, 3 * HID);
    transpose_split<<<dim3(HID / 32, HID / 32), dim3(32, 8)>>>(Wout, woh, wol, HID, HID);

    // 1) QKV projection (mma.sync bf16-split) + bias -> g_qkv [3,B,H,S,Dh] fp32
    gemm_tc<<<dim3(3 * HID / 128, MTOT / 128), 256, GT_SMEM>>>(
        xh, xl, wqh, wql, bqkv, nullptr, MTOT, 3 * HID, HID, 1);

    // 2) Attention -> g_attn_h/l [B,S,H*Dh] (bf16 split)
    attn_kernel<<<dim3(SEQ / 64, BATCH * HEADS), 256, ATTN_SMEM>>>();

    // 3) Output projection (mma.sync bf16-split) + bias -> out
    gemm_tc<<<dim3(HID / 128, MTOT / 128), 256, GT_SMEM>>>(
        ath, atl, woh, wol, bout, out, MTOT, HID, HID, 0);
}